// round 12
// baseline (speedup 1.0000x reference)
#include <cuda_runtime.h>
#include <math.h>

// Problem dims
#define B_   4
#define N_   1024
#define C_   768
#define D_   12
#define H_   12
#define HD_  64
#define FF_  3072
#define M_   (B_ * N_)     // 4096 rows
#define C3_  (3 * C_)      // 2304

// ---------------------------------------------------------------------------
// Scratch (static __device__ — no allocations allowed)
// ---------------------------------------------------------------------------
__device__ float g_x[M_ * C_];          // residual stream
__device__ float g_ln[M_ * C_];         // LN output
__device__ float g_qkv[M_ * C3_];       // fused QKV
__device__ float g_ao[M_ * C_];         // attention output [b,n,h*64+d]
__device__ float g_ffn[M_ * FF_];       // MLP hidden
__device__ float g_sc[B_ * H_ * N_ * N_]; // attention scores (201 MB)

// ---------------------------------------------------------------------------
// Elementwise add (x + pos_x)
// ---------------------------------------------------------------------------
__global__ void add_k(float* __restrict__ o, const float* __restrict__ a,
                      const float* __restrict__ b) {
    int i = blockIdx.x * blockDim.x + threadIdx.x;
    o[i] = a[i] + b[i];
}

// ---------------------------------------------------------------------------
// Block reductions (256 threads)
// ---------------------------------------------------------------------------
__device__ __forceinline__ float blk_sum(float v, float* sh) {
    #pragma unroll
    for (int o = 16; o > 0; o >>= 1) v += __shfl_xor_sync(0xffffffffu, v, o);
    int tid = threadIdx.x;
    if ((tid & 31) == 0) sh[tid >> 5] = v;
    __syncthreads();
    float t = 0.f;
    #pragma unroll
    for (int i = 0; i < 8; i++) t += sh[i];
    __syncthreads();
    return t;
}

__device__ __forceinline__ float blk_max(float v, float* sh) {
    #pragma unroll
    for (int o = 16; o > 0; o >>= 1) v = fmaxf(v, __shfl_xor_sync(0xffffffffu, v, o));
    int tid = threadIdx.x;
    if ((tid & 31) == 0) sh[tid >> 5] = v;
    __syncthreads();
    float t = -3.4e38f;
    #pragma unroll
    for (int i = 0; i < 8; i++) t = fmaxf(t, sh[i]);
    __syncthreads();
    return t;
}

// ---------------------------------------------------------------------------
// LayerNorm over last dim (C=768). One block (256 thr) per row.
// ---------------------------------------------------------------------------
__global__ void ln_k(const float* __restrict__ in, const float* __restrict__ g,
                     const float* __restrict__ be, float* __restrict__ out) {
    __shared__ float sh[8];
    const long row = blockIdx.x;
    const float* x = in + row * C_;
    float* o = out + row * C_;
    const int tid = threadIdx.x;
    float v0 = x[tid], v1 = x[tid + 256], v2 = x[tid + 512];
    float mu = blk_sum(v0 + v1 + v2, sh) * (1.f / C_);
    float d0 = v0 - mu, d1 = v1 - mu, d2 = v2 - mu;
    float var = blk_sum(d0 * d0 + d1 * d1 + d2 * d2, sh) * (1.f / C_);
    float r = rsqrtf(var + 1e-5f);
    o[tid]       = d0 * r * g[tid]       + be[tid];
    o[tid + 256] = d1 * r * g[tid + 256] + be[tid + 256];
    o[tid + 512] = d2 * r * g[tid + 512] + be[tid + 512];
}

// ---------------------------------------------------------------------------
// Row softmax over 1024 keys, applying scale 1/sqrt(64) before exp.
// One block (256 thr) per row; in-place.
// ---------------------------------------------------------------------------
__global__ void softmax_k(float* __restrict__ s) {
    __shared__ float sh[8];
    float* p = s + (long)blockIdx.x * N_;
    const int tid = threadIdx.x;
    float v0 = p[tid], v1 = p[tid + 256], v2 = p[tid + 512], v3 = p[tid + 768];
    float m = blk_max(fmaxf(fmaxf(v0, v1), fmaxf(v2, v3)), sh);
    const float sc = 0.125f;
    float e0 = __expf((v0 - m) * sc);
    float e1 = __expf((v1 - m) * sc);
    float e2 = __expf((v2 - m) * sc);
    float e3 = __expf((v3 - m) * sc);
    float r = 1.f / blk_sum(e0 + e1 + e2 + e3, sh);
    p[tid] = e0 * r; p[tid + 256] = e1 * r; p[tid + 512] = e2 * r; p[tid + 768] = e3 * r;
}

// ---------------------------------------------------------------------------
// Tiled SGEMM:  C[m,n] = sum_k A[m,k] * B(n,k)  (+ epilogue)
//   BT=false: B element (n,k) at Bm[n*ldb + k]   (weights stored [out,in])
//   BT=true : B element (n,k) at Bm[k*ldb + n]   (e.g. V^T view)
// Batched over blockIdx.z with two-level stride decomposition z = zb*hdiv+zh.
// EPI: 0 none | 1 +bias | 2 +bias, exact GELU | 3 +bias, +res (residual add)
// All M,N divisible by BM,BN; K divisible by 16. 256 threads.
// ---------------------------------------------------------------------------
template<int BM, int BN, int TM, int TN, bool BT, int EPI>
__global__ void __launch_bounds__(256, 2) sgemm_k(
    const float* __restrict__ A, const float* __restrict__ Bm,
    const float* __restrict__ bias, const float* __restrict__ res,
    float* __restrict__ Co,
    int K, int lda, int ldb, int ldc, int hdiv,
    long sAo, long sAi, long sBo, long sBi, long sCo, long sCi)
{
    constexpr int BK = 16;
    constexpr int TX = BN / TN;              // threads along n
    static_assert(TX * (BM / TM) == 256, "thread count");
    static_assert((TM & 1) == 0 && (TN & 1) == 0, "even frags");

    const int tid  = threadIdx.x;
    const int tcol = tid % TX;
    const int trow = tid / TX;

    const int z  = blockIdx.z;
    const int zb = z / hdiv;
    const int zh = z - zb * hdiv;
    const float* Ab = A  + zb * sAo + zh * sAi;
    const float* Bb = Bm + zb * sBo + zh * sBi;
    float*       Cb = Co + zb * sCo + zh * sCi;

    const int row0 = blockIdx.y * BM;
    const int col0 = blockIdx.x * BN;

    __shared__ float As[BK][BM + 4];
    __shared__ float Bs[BK][BN + 4];

    float acc[TM][TN];
    #pragma unroll
    for (int i = 0; i < TM; i++)
        #pragma unroll
        for (int j = 0; j < TN; j++) acc[i][j] = 0.f;

    for (int k0 = 0; k0 < K; k0 += BK) {
        // ---- load A tile (BM x BK), transpose into As[k][m]
        #pragma unroll
        for (int i = 0; i < (BM * BK) / 1024; i++) {
            int f  = tid + i * 256;
            int m  = f >> 2;              // BK/4 = 4 float4 per row
            int kq = (f & 3) << 2;
            const float4 v = *reinterpret_cast<const float4*>(
                Ab + (long)(row0 + m) * lda + k0 + kq);
            As[kq + 0][m] = v.x; As[kq + 1][m] = v.y;
            As[kq + 2][m] = v.z; As[kq + 3][m] = v.w;
        }
        // ---- load B tile
        if constexpr (!BT) {
            #pragma unroll
            for (int i = 0; i < (BN * BK) / 1024; i++) {
                int f  = tid + i * 256;
                int n  = f >> 2;
                int kq = (f & 3) << 2;
                const float4 v = *reinterpret_cast<const float4*>(
                    Bb + (long)(col0 + n) * ldb + k0 + kq);
                Bs[kq + 0][n] = v.x; Bs[kq + 1][n] = v.y;
                Bs[kq + 2][n] = v.z; Bs[kq + 3][n] = v.w;
            }
        } else {
            #pragma unroll
            for (int i = 0; i < (BK * BN) / 1024; i++) {
                int f  = tid + i * 256;
                int k  = f / (BN / 4);
                int nq = (f % (BN / 4)) << 2;
                *reinterpret_cast<float4*>(&Bs[k][nq]) =
                    *reinterpret_cast<const float4*>(
                        Bb + (long)(k0 + k) * ldb + col0 + nq);
            }
        }
        __syncthreads();

        #pragma unroll
        for (int kk = 0; kk < BK; kk++) {
            float ar[TM], br[TN];
            *reinterpret_cast<float4*>(&ar[0]) =
                *reinterpret_cast<const float4*>(&As[kk][trow * (TM / 2)]);
            *reinterpret_cast<float4*>(&ar[TM / 2]) =
                *reinterpret_cast<const float4*>(&As[kk][BM / 2 + trow * (TM / 2)]);
            if constexpr (TN == 8) {
                *reinterpret_cast<float4*>(&br[0]) =
                    *reinterpret_cast<const float4*>(&Bs[kk][tcol * 4]);
                *reinterpret_cast<float4*>(&br[4]) =
                    *reinterpret_cast<const float4*>(&Bs[kk][BN / 2 + tcol * 4]);
            } else {
                *reinterpret_cast<float2*>(&br[0]) =
                    *reinterpret_cast<const float2*>(&Bs[kk][tcol * 2]);
                *reinterpret_cast<float2*>(&br[2]) =
                    *reinterpret_cast<const float2*>(&Bs[kk][BN / 2 + tcol * 2]);
            }
            #pragma unroll
            for (int i = 0; i < TM; i++)
                #pragma unroll
                for (int j = 0; j < TN; j++)
                    acc[i][j] = fmaf(ar[i], br[j], acc[i][j]);
        }
        __syncthreads();
    }

    // ---- epilogue
    #pragma unroll
    for (int hi = 0; hi < 2; hi++)
        #pragma unroll
        for (int i = 0; i < TM / 2; i++) {
            const int  m  = row0 + hi * (BM / 2) + trow * (TM / 2) + i;
            const long ro = (long)m * ldc;
            #pragma unroll
            for (int hj = 0; hj < 2; hj++)
                #pragma unroll
                for (int j = 0; j < TN / 2; j++) {
                    const int n = col0 + hj * (BN / 2) + tcol * (TN / 2) + j;
                    float v = acc[hi * (TM / 2) + i][hj * (TN / 2) + j];
                    if constexpr (EPI >= 1) v += bias[n];
                    if constexpr (EPI == 2)
                        v = 0.5f * v * (1.f + erff(v * 0.70710678118654752f));
                    if constexpr (EPI == 3) v += res[ro + n];
                    Cb[ro + n] = v;
                }
        }
}

// ---------------------------------------------------------------------------
// Host launch — 110 kernel launches, all graph-capturable.
// ---------------------------------------------------------------------------
extern "C" void kernel_launch(void* const* d_in, const int* in_sizes, int n_in,
                              void* d_out, int out_size) {
    (void)in_sizes; (void)n_in; (void)out_size;
    const float* x     = (const float*)d_in[0];
    const float* posx  = (const float*)d_in[1];
    const float* qkvw  = (const float*)d_in[2];
    const float* qkvb  = (const float*)d_in[3];
    const float* projw = (const float*)d_in[4];
    const float* projb = (const float*)d_in[5];
    const float* f1w   = (const float*)d_in[6];
    const float* f1b   = (const float*)d_in[7];
    const float* f2w   = (const float*)d_in[8];
    const float* f2b   = (const float*)d_in[9];
    const float* ln1g  = (const float*)d_in[10];
    const float* ln1b  = (const float*)d_in[11];
    const float* ln2g  = (const float*)d_in[12];
    const float* ln2b  = (const float*)d_in[13];
    const float* nfg   = (const float*)d_in[14];
    const float* nfb   = (const float*)d_in[15];
    float* out = (float*)d_out;

    float *px, *pln, *pqkv, *pao, *pffn, *psc;
    cudaGetSymbolAddress((void**)&px,   g_x);
    cudaGetSymbolAddress((void**)&pln,  g_ln);
    cudaGetSymbolAddress((void**)&pqkv, g_qkv);
    cudaGetSymbolAddress((void**)&pao,  g_ao);
    cudaGetSymbolAddress((void**)&pffn, g_ffn);
    cudaGetSymbolAddress((void**)&psc,  g_sc);

    // x = x + pos_x (once)
    add_k<<<(M_ * C_) / 256, 256>>>(px, x, posx);

    for (int l = 0; l < D_; l++) {
        const float* qw = qkvw  + (long)l * C3_ * C_;
        const float* qb = qkvb  + (long)l * C3_;
        const float* pw = projw + (long)l * C_ * C_;
        const float* pb = projb + (long)l * C_;
        const float* w1 = f1w   + (long)l * FF_ * C_;
        const float* b1 = f1b   + (long)l * FF_;
        const float* w2 = f2w   + (long)l * C_ * FF_;
        const float* b2 = f2b   + (long)l * C_;

        // h = LN1(x)
        ln_k<<<M_, 256>>>(px, ln1g + l * C_, ln1b + l * C_, pln);

        // qkv = h @ qkv_w^T + qkv_b : [4096,2304]
        sgemm_k<128,128,8,8,false,1><<<dim3(C3_/128, M_/128, 1), 256>>>(
            pln, qw, qb, nullptr, pqkv,
            C_, C_, C_, C3_, 1, 0,0,0,0,0,0);

        // S = Q K^T : batched (b,h), [1024,1024], K=64
        sgemm_k<128,128,8,8,false,0><<<dim3(N_/128, N_/128, B_*H_), 256>>>(
            pqkv, pqkv + C_, nullptr, nullptr, psc,
            HD_, C3_, C3_, N_, H_,
            (long)N_ * C3_, HD_, (long)N_ * C3_, HD_,
            (long)H_ * N_ * N_, (long)N_ * N_);

        // softmax(S * scale) rows
        softmax_k<<<B_ * H_ * N_, 256>>>(psc);

        // O = P V : batched, [1024,64], K=1024 (V accessed transposed)
        sgemm_k<128,64,8,4,true,0><<<dim3(1, N_/128, B_*H_), 256>>>(
            psc, pqkv + 2 * C_, nullptr, nullptr, pao,
            N_, N_, C3_, C_, H_,
            (long)H_ * N_ * N_, (long)N_ * N_, (long)N_ * C3_, HD_,
            (long)N_ * C_, HD_);

        // x = x + (O @ proj_w^T + proj_b)
        sgemm_k<128,128,8,8,false,3><<<dim3(C_/128, M_/128, 1), 256>>>(
            pao, pw, pb, px, px,
            C_, C_, C_, C_, 1, 0,0,0,0,0,0);

        // h2 = LN2(x)
        ln_k<<<M_, 256>>>(px, ln2g + l * C_, ln2b + l * C_, pln);

        // hid = gelu(h2 @ fc1_w^T + fc1_b) : [4096,3072]
        sgemm_k<128,128,8,8,false,2><<<dim3(FF_/128, M_/128, 1), 256>>>(
            pln, w1, b1, nullptr, pffn,
            C_, C_, C_, FF_, 1, 0,0,0,0,0,0);

        // x = x + (hid @ fc2_w^T + fc2_b)
        sgemm_k<128,128,8,8,false,3><<<dim3(C_/128, M_/128, 1), 256>>>(
            pffn, w2, b2, px, px,
            FF_, FF_, FF_, C_, 1, 0,0,0,0,0,0);
    }

    // final post-norm -> output
    ln_k<<<M_, 256>>>(px, nfg, nfb, out);
}

// round 13
// speedup vs baseline: 1.0001x; 1.0001x over previous
#include <cuda_runtime.h>
#include <math.h>

// Problem dims
#define B_   4
#define N_   1024
#define C_   768
#define D_   12
#define H_   12
#define HD_  64
#define FF_  3072
#define M_   (B_ * N_)     // 4096 rows
#define C3_  (3 * C_)      // 2304

// ---------------------------------------------------------------------------
// Scratch (static __device__ — no allocations allowed)
// ---------------------------------------------------------------------------
__device__ float g_x[M_ * C_];          // residual stream
__device__ float g_ln[M_ * C_];         // LN output
__device__ float g_qkv[M_ * C3_];       // fused QKV
__device__ float g_ao[M_ * C_];         // attention output [b,n,h*64+d]
__device__ float g_ffn[M_ * FF_];       // MLP hidden
__device__ float g_sc[B_ * H_ * N_ * N_]; // attention scores (201 MB)

// ---------------------------------------------------------------------------
// Elementwise add (x + pos_x)
// ---------------------------------------------------------------------------
__global__ void add_k(float* __restrict__ o, const float* __restrict__ a,
                      const float* __restrict__ b) {
    int i = blockIdx.x * blockDim.x + threadIdx.x;
    o[i] = a[i] + b[i];
}

// ---------------------------------------------------------------------------
// Block reductions (256 threads)
// ---------------------------------------------------------------------------
__device__ __forceinline__ float blk_sum(float v, float* sh) {
    #pragma unroll
    for (int o = 16; o > 0; o >>= 1) v += __shfl_xor_sync(0xffffffffu, v, o);
    int tid = threadIdx.x;
    if ((tid & 31) == 0) sh[tid >> 5] = v;
    __syncthreads();
    float t = 0.f;
    #pragma unroll
    for (int i = 0; i < 8; i++) t += sh[i];
    __syncthreads();
    return t;
}

__device__ __forceinline__ float blk_max(float v, float* sh) {
    #pragma unroll
    for (int o = 16; o > 0; o >>= 1) v = fmaxf(v, __shfl_xor_sync(0xffffffffu, v, o));
    int tid = threadIdx.x;
    if ((tid & 31) == 0) sh[tid >> 5] = v;
    __syncthreads();
    float t = -3.4e38f;
    #pragma unroll
    for (int i = 0; i < 8; i++) t = fmaxf(t, sh[i]);
    __syncthreads();
    return t;
}

// ---------------------------------------------------------------------------
// LayerNorm over last dim (C=768). One block (256 thr) per row.
// ---------------------------------------------------------------------------
__global__ void ln_k(const float* __restrict__ in, const float* __restrict__ g,
                     const float* __restrict__ be, float* __restrict__ out) {
    __shared__ float sh[8];
    const long row = blockIdx.x;
    const float* x = in + row * C_;
    float* o = out + row * C_;
    const int tid = threadIdx.x;
    float v0 = x[tid], v1 = x[tid + 256], v2 = x[tid + 512];
    float mu = blk_sum(v0 + v1 + v2, sh) * (1.f / C_);
    float d0 = v0 - mu, d1 = v1 - mu, d2 = v2 - mu;
    float var = blk_sum(d0 * d0 + d1 * d1 + d2 * d2, sh) * (1.f / C_);
    float r = rsqrtf(var + 1e-5f);
    o[tid]       = d0 * r * g[tid]       + be[tid];
    o[tid + 256] = d1 * r * g[tid + 256] + be[tid + 256];
    o[tid + 512] = d2 * r * g[tid + 512] + be[tid + 512];
}

// ---------------------------------------------------------------------------
// Row softmax over 1024 keys, applying scale 1/sqrt(64) before exp.
// One block (256 thr) per row; in-place.
// ---------------------------------------------------------------------------
__global__ void softmax_k(float* __restrict__ s) {
    __shared__ float sh[8];
    float* p = s + (long)blockIdx.x * N_;
    const int tid = threadIdx.x;
    float v0 = p[tid], v1 = p[tid + 256], v2 = p[tid + 512], v3 = p[tid + 768];
    float m = blk_max(fmaxf(fmaxf(v0, v1), fmaxf(v2, v3)), sh);
    const float sc = 0.125f;
    float e0 = __expf((v0 - m) * sc);
    float e1 = __expf((v1 - m) * sc);
    float e2 = __expf((v2 - m) * sc);
    float e3 = __expf((v3 - m) * sc);
    float r = 1.f / blk_sum(e0 + e1 + e2 + e3, sh);
    p[tid] = e0 * r; p[tid + 256] = e1 * r; p[tid + 512] = e2 * r; p[tid + 768] = e3 * r;
}

// ---------------------------------------------------------------------------
// Tiled SGEMM:  C[m,n] = sum_k A[m,k] * B(n,k)  (+ epilogue)
//   BT=false: B element (n,k) at Bm[n*ldb + k]   (weights stored [out,in])
//   BT=true : B element (n,k) at Bm[k*ldb + n]   (e.g. V^T view)
// Batched over blockIdx.z with two-level stride decomposition z = zb*hdiv+zh.
// EPI: 0 none | 1 +bias | 2 +bias, exact GELU | 3 +bias, +res (residual add)
// All M,N divisible by BM,BN; K divisible by 16. 256 threads.
// ---------------------------------------------------------------------------
template<int BM, int BN, int TM, int TN, bool BT, int EPI>
__global__ void __launch_bounds__(256, 2) sgemm_k(
    const float* __restrict__ A, const float* __restrict__ Bm,
    const float* __restrict__ bias, const float* __restrict__ res,
    float* __restrict__ Co,
    int K, int lda, int ldb, int ldc, int hdiv,
    long sAo, long sAi, long sBo, long sBi, long sCo, long sCi)
{
    constexpr int BK = 16;
    constexpr int TX = BN / TN;              // threads along n
    static_assert(TX * (BM / TM) == 256, "thread count");
    static_assert((TM & 1) == 0 && (TN & 1) == 0, "even frags");

    const int tid  = threadIdx.x;
    const int tcol = tid % TX;
    const int trow = tid / TX;

    const int z  = blockIdx.z;
    const int zb = z / hdiv;
    const int zh = z - zb * hdiv;
    const float* Ab = A  + zb * sAo + zh * sAi;
    const float* Bb = Bm + zb * sBo + zh * sBi;
    float*       Cb = Co + zb * sCo + zh * sCi;

    const int row0 = blockIdx.y * BM;
    const int col0 = blockIdx.x * BN;

    __shared__ float As[BK][BM + 4];
    __shared__ float Bs[BK][BN + 4];

    float acc[TM][TN];
    #pragma unroll
    for (int i = 0; i < TM; i++)
        #pragma unroll
        for (int j = 0; j < TN; j++) acc[i][j] = 0.f;

    for (int k0 = 0; k0 < K; k0 += BK) {
        // ---- load A tile (BM x BK), transpose into As[k][m]
        #pragma unroll
        for (int i = 0; i < (BM * BK) / 1024; i++) {
            int f  = tid + i * 256;
            int m  = f >> 2;              // BK/4 = 4 float4 per row
            int kq = (f & 3) << 2;
            const float4 v = *reinterpret_cast<const float4*>(
                Ab + (long)(row0 + m) * lda + k0 + kq);
            As[kq + 0][m] = v.x; As[kq + 1][m] = v.y;
            As[kq + 2][m] = v.z; As[kq + 3][m] = v.w;
        }
        // ---- load B tile
        if constexpr (!BT) {
            #pragma unroll
            for (int i = 0; i < (BN * BK) / 1024; i++) {
                int f  = tid + i * 256;
                int n  = f >> 2;
                int kq = (f & 3) << 2;
                const float4 v = *reinterpret_cast<const float4*>(
                    Bb + (long)(col0 + n) * ldb + k0 + kq);
                Bs[kq + 0][n] = v.x; Bs[kq + 1][n] = v.y;
                Bs[kq + 2][n] = v.z; Bs[kq + 3][n] = v.w;
            }
        } else {
            #pragma unroll
            for (int i = 0; i < (BK * BN) / 1024; i++) {
                int f  = tid + i * 256;
                int k  = f / (BN / 4);
                int nq = (f % (BN / 4)) << 2;
                *reinterpret_cast<float4*>(&Bs[k][nq]) =
                    *reinterpret_cast<const float4*>(
                        Bb + (long)(k0 + k) * ldb + col0 + nq);
            }
        }
        __syncthreads();

        #pragma unroll
        for (int kk = 0; kk < BK; kk++) {
            float ar[TM], br[TN];
            *reinterpret_cast<float4*>(&ar[0]) =
                *reinterpret_cast<const float4*>(&As[kk][trow * (TM / 2)]);
            *reinterpret_cast<float4*>(&ar[TM / 2]) =
                *reinterpret_cast<const float4*>(&As[kk][BM / 2 + trow * (TM / 2)]);
            if constexpr (TN == 8) {
                *reinterpret_cast<float4*>(&br[0]) =
                    *reinterpret_cast<const float4*>(&Bs[kk][tcol * 4]);
                *reinterpret_cast<float4*>(&br[4]) =
                    *reinterpret_cast<const float4*>(&Bs[kk][BN / 2 + tcol * 4]);
            } else {
                *reinterpret_cast<float2*>(&br[0]) =
                    *reinterpret_cast<const float2*>(&Bs[kk][tcol * 2]);
                *reinterpret_cast<float2*>(&br[2]) =
                    *reinterpret_cast<const float2*>(&Bs[kk][BN / 2 + tcol * 2]);
            }
            #pragma unroll
            for (int i = 0; i < TM; i++)
                #pragma unroll
                for (int j = 0; j < TN; j++)
                    acc[i][j] = fmaf(ar[i], br[j], acc[i][j]);
        }
        __syncthreads();
    }

    // ---- epilogue
    #pragma unroll
    for (int hi = 0; hi < 2; hi++)
        #pragma unroll
        for (int i = 0; i < TM / 2; i++) {
            const int  m  = row0 + hi * (BM / 2) + trow * (TM / 2) + i;
            const long ro = (long)m * ldc;
            #pragma unroll
            for (int hj = 0; hj < 2; hj++)
                #pragma unroll
                for (int j = 0; j < TN / 2; j++) {
                    const int n = col0 + hj * (BN / 2) + tcol * (TN / 2) + j;
                    float v = acc[hi * (TM / 2) + i][hj * (TN / 2) + j];
                    if constexpr (EPI >= 1) v += bias[n];
                    if constexpr (EPI == 2)
                        v = 0.5f * v * (1.f + erff(v * 0.70710678118654752f));
                    if constexpr (EPI == 3) v += res[ro + n];
                    Cb[ro + n] = v;
                }
        }
}

// ---------------------------------------------------------------------------
// Host launch — 110 kernel launches, all graph-capturable.
// ---------------------------------------------------------------------------
extern "C" void kernel_launch(void* const* d_in, const int* in_sizes, int n_in,
                              void* d_out, int out_size) {
    (void)in_sizes; (void)n_in; (void)out_size;
    const float* x     = (const float*)d_in[0];
    const float* posx  = (const float*)d_in[1];
    const float* qkvw  = (const float*)d_in[2];
    const float* qkvb  = (const float*)d_in[3];
    const float* projw = (const float*)d_in[4];
    const float* projb = (const float*)d_in[5];
    const float* f1w   = (const float*)d_in[6];
    const float* f1b   = (const float*)d_in[7];
    const float* f2w   = (const float*)d_in[8];
    const float* f2b   = (const float*)d_in[9];
    const float* ln1g  = (const float*)d_in[10];
    const float* ln1b  = (const float*)d_in[11];
    const float* ln2g  = (const float*)d_in[12];
    const float* ln2b  = (const float*)d_in[13];
    const float* nfg   = (const float*)d_in[14];
    const float* nfb   = (const float*)d_in[15];
    float* out = (float*)d_out;

    float *px, *pln, *pqkv, *pao, *pffn, *psc;
    cudaGetSymbolAddress((void**)&px,   g_x);
    cudaGetSymbolAddress((void**)&pln,  g_ln);
    cudaGetSymbolAddress((void**)&pqkv, g_qkv);
    cudaGetSymbolAddress((void**)&pao,  g_ao);
    cudaGetSymbolAddress((void**)&pffn, g_ffn);
    cudaGetSymbolAddress((void**)&psc,  g_sc);

    // x = x + pos_x (once)
    add_k<<<(M_ * C_) / 256, 256>>>(px, x, posx);

    for (int l = 0; l < D_; l++) {
        const float* qw = qkvw  + (long)l * C3_ * C_;
        const float* qb = qkvb  + (long)l * C3_;
        const float* pw = projw + (long)l * C_ * C_;
        const float* pb = projb + (long)l * C_;
        const float* w1 = f1w   + (long)l * FF_ * C_;
        const float* b1 = f1b   + (long)l * FF_;
        const float* w2 = f2w   + (long)l * C_ * FF_;
        const float* b2 = f2b   + (long)l * C_;

        // h = LN1(x)
        ln_k<<<M_, 256>>>(px, ln1g + l * C_, ln1b + l * C_, pln);

        // qkv = h @ qkv_w^T + qkv_b : [4096,2304]
        sgemm_k<128,128,8,8,false,1><<<dim3(C3_/128, M_/128, 1), 256>>>(
            pln, qw, qb, nullptr, pqkv,
            C_, C_, C_, C3_, 1, 0,0,0,0,0,0);

        // S = Q K^T : batched (b,h), [1024,1024], K=64
        sgemm_k<128,128,8,8,false,0><<<dim3(N_/128, N_/128, B_*H_), 256>>>(
            pqkv, pqkv + C_, nullptr, nullptr, psc,
            HD_, C3_, C3_, N_, H_,
            (long)N_ * C3_, HD_, (long)N_ * C3_, HD_,
            (long)H_ * N_ * N_, (long)N_ * N_);

        // softmax(S * scale) rows
        softmax_k<<<B_ * H_ * N_, 256>>>(psc);

        // O = P V : batched, [1024,64], K=1024 (V accessed transposed)
        sgemm_k<128,64,8,4,true,0><<<dim3(1, N_/128, B_*H_), 256>>>(
            psc, pqkv + 2 * C_, nullptr, nullptr, pao,
            N_, N_, C3_, C_, H_,
            (long)H_ * N_ * N_, (long)N_ * N_, (long)N_ * C3_, HD_,
            (long)N_ * C_, HD_);

        // x = x + (O @ proj_w^T + proj_b)
        sgemm_k<128,128,8,8,false,3><<<dim3(C_/128, M_/128, 1), 256>>>(
            pao, pw, pb, px, px,
            C_, C_, C_, C_, 1, 0,0,0,0,0,0);

        // h2 = LN2(x)
        ln_k<<<M_, 256>>>(px, ln2g + l * C_, ln2b + l * C_, pln);

        // hid = gelu(h2 @ fc1_w^T + fc1_b) : [4096,3072]
        sgemm_k<128,128,8,8,false,2><<<dim3(FF_/128, M_/128, 1), 256>>>(
            pln, w1, b1, nullptr, pffn,
            C_, C_, C_, FF_, 1, 0,0,0,0,0,0);

        // x = x + (hid @ fc2_w^T + fc2_b)
        sgemm_k<128,128,8,8,false,3><<<dim3(C_/128, M_/128, 1), 256>>>(
            pffn, w2, b2, px, px,
            FF_, FF_, FF_, C_, 1, 0,0,0,0,0,0);
    }

    // final post-norm -> output
    ln_k<<<M_, 256>>>(px, nfg, nfb, out);
}

// round 14
// speedup vs baseline: 1.0007x; 1.0006x over previous
#include <cuda_runtime.h>
#include <math.h>

// Problem dims
#define B_   4
#define N_   1024
#define C_   768
#define D_   12
#define H_   12
#define HD_  64
#define FF_  3072
#define M_   (B_ * N_)     // 4096 rows
#define C3_  (3 * C_)      // 2304

// ---------------------------------------------------------------------------
// Scratch (static __device__ — no allocations allowed)
// ---------------------------------------------------------------------------
__device__ float g_x[M_ * C_];          // residual stream
__device__ float g_ln[M_ * C_];         // LN output
__device__ float g_qkv[M_ * C3_];       // fused QKV
__device__ float g_ao[M_ * C_];         // attention output [b,n,h*64+d]
__device__ float g_ffn[M_ * FF_];       // MLP hidden
__device__ float g_sc[B_ * H_ * N_ * N_]; // attention scores (201 MB)

// ---------------------------------------------------------------------------
// Elementwise add (x + pos_x)
// ---------------------------------------------------------------------------
__global__ void add_k(float* __restrict__ o, const float* __restrict__ a,
                      const float* __restrict__ b) {
    int i = blockIdx.x * blockDim.x + threadIdx.x;
    o[i] = a[i] + b[i];
}

// ---------------------------------------------------------------------------
// Block reductions (256 threads)
// ---------------------------------------------------------------------------
__device__ __forceinline__ float blk_sum(float v, float* sh) {
    #pragma unroll
    for (int o = 16; o > 0; o >>= 1) v += __shfl_xor_sync(0xffffffffu, v, o);
    int tid = threadIdx.x;
    if ((tid & 31) == 0) sh[tid >> 5] = v;
    __syncthreads();
    float t = 0.f;
    #pragma unroll
    for (int i = 0; i < 8; i++) t += sh[i];
    __syncthreads();
    return t;
}

__device__ __forceinline__ float blk_max(float v, float* sh) {
    #pragma unroll
    for (int o = 16; o > 0; o >>= 1) v = fmaxf(v, __shfl_xor_sync(0xffffffffu, v, o));
    int tid = threadIdx.x;
    if ((tid & 31) == 0) sh[tid >> 5] = v;
    __syncthreads();
    float t = -3.4e38f;
    #pragma unroll
    for (int i = 0; i < 8; i++) t = fmaxf(t, sh[i]);
    __syncthreads();
    return t;
}

// ---------------------------------------------------------------------------
// LayerNorm over last dim (C=768). One block (256 thr) per row.
// ---------------------------------------------------------------------------
__global__ void ln_k(const float* __restrict__ in, const float* __restrict__ g,
                     const float* __restrict__ be, float* __restrict__ out) {
    __shared__ float sh[8];
    const long row = blockIdx.x;
    const float* x = in + row * C_;
    float* o = out + row * C_;
    const int tid = threadIdx.x;
    float v0 = x[tid], v1 = x[tid + 256], v2 = x[tid + 512];
    float mu = blk_sum(v0 + v1 + v2, sh) * (1.f / C_);
    float d0 = v0 - mu, d1 = v1 - mu, d2 = v2 - mu;
    float var = blk_sum(d0 * d0 + d1 * d1 + d2 * d2, sh) * (1.f / C_);
    float r = rsqrtf(var + 1e-5f);
    o[tid]       = d0 * r * g[tid]       + be[tid];
    o[tid + 256] = d1 * r * g[tid + 256] + be[tid + 256];
    o[tid + 512] = d2 * r * g[tid + 512] + be[tid + 512];
}

// ---------------------------------------------------------------------------
// Row softmax over 1024 keys, applying scale 1/sqrt(64) before exp.
// One block (256 thr) per row; in-place.
// ---------------------------------------------------------------------------
__global__ void softmax_k(float* __restrict__ s) {
    __shared__ float sh[8];
    float* p = s + (long)blockIdx.x * N_;
    const int tid = threadIdx.x;
    float v0 = p[tid], v1 = p[tid + 256], v2 = p[tid + 512], v3 = p[tid + 768];
    float m = blk_max(fmaxf(fmaxf(v0, v1), fmaxf(v2, v3)), sh);
    const float sc = 0.125f;
    float e0 = __expf((v0 - m) * sc);
    float e1 = __expf((v1 - m) * sc);
    float e2 = __expf((v2 - m) * sc);
    float e3 = __expf((v3 - m) * sc);
    float r = 1.f / blk_sum(e0 + e1 + e2 + e3, sh);
    p[tid] = e0 * r; p[tid + 256] = e1 * r; p[tid + 512] = e2 * r; p[tid + 768] = e3 * r;
}

// ---------------------------------------------------------------------------
// Tiled SGEMM:  C[m,n] = sum_k A[m,k] * B(n,k)  (+ epilogue)
//   BT=false: B element (n,k) at Bm[n*ldb + k]   (weights stored [out,in])
//   BT=true : B element (n,k) at Bm[k*ldb + n]   (e.g. V^T view)
// Batched over blockIdx.z with two-level stride decomposition z = zb*hdiv+zh.
// EPI: 0 none | 1 +bias | 2 +bias, exact GELU | 3 +bias, +res (residual add)
// All M,N divisible by BM,BN; K divisible by 16. 256 threads.
// ---------------------------------------------------------------------------
template<int BM, int BN, int TM, int TN, bool BT, int EPI>
__global__ void __launch_bounds__(256, 2) sgemm_k(
    const float* __restrict__ A, const float* __restrict__ Bm,
    const float* __restrict__ bias, const float* __restrict__ res,
    float* __restrict__ Co,
    int K, int lda, int ldb, int ldc, int hdiv,
    long sAo, long sAi, long sBo, long sBi, long sCo, long sCi)
{
    constexpr int BK = 16;
    constexpr int TX = BN / TN;              // threads along n
    static_assert(TX * (BM / TM) == 256, "thread count");
    static_assert((TM & 1) == 0 && (TN & 1) == 0, "even frags");

    const int tid  = threadIdx.x;
    const int tcol = tid % TX;
    const int trow = tid / TX;

    const int z  = blockIdx.z;
    const int zb = z / hdiv;
    const int zh = z - zb * hdiv;
    const float* Ab = A  + zb * sAo + zh * sAi;
    const float* Bb = Bm + zb * sBo + zh * sBi;
    float*       Cb = Co + zb * sCo + zh * sCi;

    const int row0 = blockIdx.y * BM;
    const int col0 = blockIdx.x * BN;

    __shared__ float As[BK][BM + 4];
    __shared__ float Bs[BK][BN + 4];

    float acc[TM][TN];
    #pragma unroll
    for (int i = 0; i < TM; i++)
        #pragma unroll
        for (int j = 0; j < TN; j++) acc[i][j] = 0.f;

    for (int k0 = 0; k0 < K; k0 += BK) {
        // ---- load A tile (BM x BK), transpose into As[k][m]
        #pragma unroll
        for (int i = 0; i < (BM * BK) / 1024; i++) {
            int f  = tid + i * 256;
            int m  = f >> 2;              // BK/4 = 4 float4 per row
            int kq = (f & 3) << 2;
            const float4 v = *reinterpret_cast<const float4*>(
                Ab + (long)(row0 + m) * lda + k0 + kq);
            As[kq + 0][m] = v.x; As[kq + 1][m] = v.y;
            As[kq + 2][m] = v.z; As[kq + 3][m] = v.w;
        }
        // ---- load B tile
        if constexpr (!BT) {
            #pragma unroll
            for (int i = 0; i < (BN * BK) / 1024; i++) {
                int f  = tid + i * 256;
                int n  = f >> 2;
                int kq = (f & 3) << 2;
                const float4 v = *reinterpret_cast<const float4*>(
                    Bb + (long)(col0 + n) * ldb + k0 + kq);
                Bs[kq + 0][n] = v.x; Bs[kq + 1][n] = v.y;
                Bs[kq + 2][n] = v.z; Bs[kq + 3][n] = v.w;
            }
        } else {
            #pragma unroll
            for (int i = 0; i < (BK * BN) / 1024; i++) {
                int f  = tid + i * 256;
                int k  = f / (BN / 4);
                int nq = (f % (BN / 4)) << 2;
                *reinterpret_cast<float4*>(&Bs[k][nq]) =
                    *reinterpret_cast<const float4*>(
                        Bb + (long)(k0 + k) * ldb + col0 + nq);
            }
        }
        __syncthreads();

        #pragma unroll
        for (int kk = 0; kk < BK; kk++) {
            float ar[TM], br[TN];
            *reinterpret_cast<float4*>(&ar[0]) =
                *reinterpret_cast<const float4*>(&As[kk][trow * (TM / 2)]);
            *reinterpret_cast<float4*>(&ar[TM / 2]) =
                *reinterpret_cast<const float4*>(&As[kk][BM / 2 + trow * (TM / 2)]);
            if constexpr (TN == 8) {
                *reinterpret_cast<float4*>(&br[0]) =
                    *reinterpret_cast<const float4*>(&Bs[kk][tcol * 4]);
                *reinterpret_cast<float4*>(&br[4]) =
                    *reinterpret_cast<const float4*>(&Bs[kk][BN / 2 + tcol * 4]);
            } else {
                *reinterpret_cast<float2*>(&br[0]) =
                    *reinterpret_cast<const float2*>(&Bs[kk][tcol * 2]);
                *reinterpret_cast<float2*>(&br[2]) =
                    *reinterpret_cast<const float2*>(&Bs[kk][BN / 2 + tcol * 2]);
            }
            #pragma unroll
            for (int i = 0; i < TM; i++)
                #pragma unroll
                for (int j = 0; j < TN; j++)
                    acc[i][j] = fmaf(ar[i], br[j], acc[i][j]);
        }
        __syncthreads();
    }

    // ---- epilogue
    #pragma unroll
    for (int hi = 0; hi < 2; hi++)
        #pragma unroll
        for (int i = 0; i < TM / 2; i++) {
            const int  m  = row0 + hi * (BM / 2) + trow * (TM / 2) + i;
            const long ro = (long)m * ldc;
            #pragma unroll
            for (int hj = 0; hj < 2; hj++)
                #pragma unroll
                for (int j = 0; j < TN / 2; j++) {
                    const int n = col0 + hj * (BN / 2) + tcol * (TN / 2) + j;
                    float v = acc[hi * (TM / 2) + i][hj * (TN / 2) + j];
                    if constexpr (EPI >= 1) v += bias[n];
                    if constexpr (EPI == 2)
                        v = 0.5f * v * (1.f + erff(v * 0.70710678118654752f));
                    if constexpr (EPI == 3) v += res[ro + n];
                    Cb[ro + n] = v;
                }
        }
}

// ---------------------------------------------------------------------------
// Host launch — 110 kernel launches, all graph-capturable.
// ---------------------------------------------------------------------------
extern "C" void kernel_launch(void* const* d_in, const int* in_sizes, int n_in,
                              void* d_out, int out_size) {
    (void)in_sizes; (void)n_in; (void)out_size;
    const float* x     = (const float*)d_in[0];
    const float* posx  = (const float*)d_in[1];
    const float* qkvw  = (const float*)d_in[2];
    const float* qkvb  = (const float*)d_in[3];
    const float* projw = (const float*)d_in[4];
    const float* projb = (const float*)d_in[5];
    const float* f1w   = (const float*)d_in[6];
    const float* f1b   = (const float*)d_in[7];
    const float* f2w   = (const float*)d_in[8];
    const float* f2b   = (const float*)d_in[9];
    const float* ln1g  = (const float*)d_in[10];
    const float* ln1b  = (const float*)d_in[11];
    const float* ln2g  = (const float*)d_in[12];
    const float* ln2b  = (const float*)d_in[13];
    const float* nfg   = (const float*)d_in[14];
    const float* nfb   = (const float*)d_in[15];
    float* out = (float*)d_out;

    float *px, *pln, *pqkv, *pao, *pffn, *psc;
    cudaGetSymbolAddress((void**)&px,   g_x);
    cudaGetSymbolAddress((void**)&pln,  g_ln);
    cudaGetSymbolAddress((void**)&pqkv, g_qkv);
    cudaGetSymbolAddress((void**)&pao,  g_ao);
    cudaGetSymbolAddress((void**)&pffn, g_ffn);
    cudaGetSymbolAddress((void**)&psc,  g_sc);

    // x = x + pos_x (once)
    add_k<<<(M_ * C_) / 256, 256>>>(px, x, posx);

    for (int l = 0; l < D_; l++) {
        const float* qw = qkvw  + (long)l * C3_ * C_;
        const float* qb = qkvb  + (long)l * C3_;
        const float* pw = projw + (long)l * C_ * C_;
        const float* pb = projb + (long)l * C_;
        const float* w1 = f1w   + (long)l * FF_ * C_;
        const float* b1 = f1b   + (long)l * FF_;
        const float* w2 = f2w   + (long)l * C_ * FF_;
        const float* b2 = f2b   + (long)l * C_;

        // h = LN1(x)
        ln_k<<<M_, 256>>>(px, ln1g + l * C_, ln1b + l * C_, pln);

        // qkv = h @ qkv_w^T + qkv_b : [4096,2304]
        sgemm_k<128,128,8,8,false,1><<<dim3(C3_/128, M_/128, 1), 256>>>(
            pln, qw, qb, nullptr, pqkv,
            C_, C_, C_, C3_, 1, 0,0,0,0,0,0);

        // S = Q K^T : batched (b,h), [1024,1024], K=64
        sgemm_k<128,128,8,8,false,0><<<dim3(N_/128, N_/128, B_*H_), 256>>>(
            pqkv, pqkv + C_, nullptr, nullptr, psc,
            HD_, C3_, C3_, N_, H_,
            (long)N_ * C3_, HD_, (long)N_ * C3_, HD_,
            (long)H_ * N_ * N_, (long)N_ * N_);

        // softmax(S * scale) rows
        softmax_k<<<B_ * H_ * N_, 256>>>(psc);

        // O = P V : batched, [1024,64], K=1024 (V accessed transposed)
        sgemm_k<128,64,8,4,true,0><<<dim3(1, N_/128, B_*H_), 256>>>(
            psc, pqkv + 2 * C_, nullptr, nullptr, pao,
            N_, N_, C3_, C_, H_,
            (long)H_ * N_ * N_, (long)N_ * N_, (long)N_ * C3_, HD_,
            (long)N_ * C_, HD_);

        // x = x + (O @ proj_w^T + proj_b)
        sgemm_k<128,128,8,8,false,3><<<dim3(C_/128, M_/128, 1), 256>>>(
            pao, pw, pb, px, px,
            C_, C_, C_, C_, 1, 0,0,0,0,0,0);

        // h2 = LN2(x)
        ln_k<<<M_, 256>>>(px, ln2g + l * C_, ln2b + l * C_, pln);

        // hid = gelu(h2 @ fc1_w^T + fc1_b) : [4096,3072]
        sgemm_k<128,128,8,8,false,2><<<dim3(FF_/128, M_/128, 1), 256>>>(
            pln, w1, b1, nullptr, pffn,
            C_, C_, C_, FF_, 1, 0,0,0,0,0,0);

        // x = x + (hid @ fc2_w^T + fc2_b)
        sgemm_k<128,128,8,8,false,3><<<dim3(C_/128, M_/128, 1), 256>>>(
            pffn, w2, b2, px, px,
            FF_, FF_, FF_, C_, 1, 0,0,0,0,0,0);
    }

    // final post-norm -> output
    ln_k<<<M_, 256>>>(px, nfg, nfb, out);
}

// round 15
// speedup vs baseline: 1.0012x; 1.0005x over previous
#include <cuda_runtime.h>
#include <math.h>

// Problem dims
#define B_   4
#define N_   1024
#define C_   768
#define D_   12
#define H_   12
#define HD_  64
#define FF_  3072
#define M_   (B_ * N_)     // 4096 rows
#define C3_  (3 * C_)      // 2304

// ---------------------------------------------------------------------------
// Scratch (static __device__ — no allocations allowed)
// ---------------------------------------------------------------------------
__device__ float g_x[M_ * C_];          // residual stream
__device__ float g_ln[M_ * C_];         // LN output
__device__ float g_qkv[M_ * C3_];       // fused QKV
__device__ float g_ao[M_ * C_];         // attention output [b,n,h*64+d]
__device__ float g_ffn[M_ * FF_];       // MLP hidden
__device__ float g_sc[B_ * H_ * N_ * N_]; // attention scores (201 MB)

// ---------------------------------------------------------------------------
// Elementwise add (x + pos_x)
// ---------------------------------------------------------------------------
__global__ void add_k(float* __restrict__ o, const float* __restrict__ a,
                      const float* __restrict__ b) {
    int i = blockIdx.x * blockDim.x + threadIdx.x;
    o[i] = a[i] + b[i];
}

// ---------------------------------------------------------------------------
// Block reductions (256 threads)
// ---------------------------------------------------------------------------
__device__ __forceinline__ float blk_sum(float v, float* sh) {
    #pragma unroll
    for (int o = 16; o > 0; o >>= 1) v += __shfl_xor_sync(0xffffffffu, v, o);
    int tid = threadIdx.x;
    if ((tid & 31) == 0) sh[tid >> 5] = v;
    __syncthreads();
    float t = 0.f;
    #pragma unroll
    for (int i = 0; i < 8; i++) t += sh[i];
    __syncthreads();
    return t;
}

__device__ __forceinline__ float blk_max(float v, float* sh) {
    #pragma unroll
    for (int o = 16; o > 0; o >>= 1) v = fmaxf(v, __shfl_xor_sync(0xffffffffu, v, o));
    int tid = threadIdx.x;
    if ((tid & 31) == 0) sh[tid >> 5] = v;
    __syncthreads();
    float t = -3.4e38f;
    #pragma unroll
    for (int i = 0; i < 8; i++) t = fmaxf(t, sh[i]);
    __syncthreads();
    return t;
}

// ---------------------------------------------------------------------------
// LayerNorm over last dim (C=768). One block (256 thr) per row.
// ---------------------------------------------------------------------------
__global__ void ln_k(const float* __restrict__ in, const float* __restrict__ g,
                     const float* __restrict__ be, float* __restrict__ out) {
    __shared__ float sh[8];
    const long row = blockIdx.x;
    const float* x = in + row * C_;
    float* o = out + row * C_;
    const int tid = threadIdx.x;
    float v0 = x[tid], v1 = x[tid + 256], v2 = x[tid + 512];
    float mu = blk_sum(v0 + v1 + v2, sh) * (1.f / C_);
    float d0 = v0 - mu, d1 = v1 - mu, d2 = v2 - mu;
    float var = blk_sum(d0 * d0 + d1 * d1 + d2 * d2, sh) * (1.f / C_);
    float r = rsqrtf(var + 1e-5f);
    o[tid]       = d0 * r * g[tid]       + be[tid];
    o[tid + 256] = d1 * r * g[tid + 256] + be[tid + 256];
    o[tid + 512] = d2 * r * g[tid + 512] + be[tid + 512];
}

// ---------------------------------------------------------------------------
// Row softmax over 1024 keys, applying scale 1/sqrt(64) before exp.
// One block (256 thr) per row; in-place.
// ---------------------------------------------------------------------------
__global__ void softmax_k(float* __restrict__ s) {
    __shared__ float sh[8];
    float* p = s + (long)blockIdx.x * N_;
    const int tid = threadIdx.x;
    float v0 = p[tid], v1 = p[tid + 256], v2 = p[tid + 512], v3 = p[tid + 768];
    float m = blk_max(fmaxf(fmaxf(v0, v1), fmaxf(v2, v3)), sh);
    const float sc = 0.125f;
    float e0 = __expf((v0 - m) * sc);
    float e1 = __expf((v1 - m) * sc);
    float e2 = __expf((v2 - m) * sc);
    float e3 = __expf((v3 - m) * sc);
    float r = 1.f / blk_sum(e0 + e1 + e2 + e3, sh);
    p[tid] = e0 * r; p[tid + 256] = e1 * r; p[tid + 512] = e2 * r; p[tid + 768] = e3 * r;
}

// ---------------------------------------------------------------------------
// Tiled SGEMM:  C[m,n] = sum_k A[m,k] * B(n,k)  (+ epilogue)
//   BT=false: B element (n,k) at Bm[n*ldb + k]   (weights stored [out,in])
//   BT=true : B element (n,k) at Bm[k*ldb + n]   (e.g. V^T view)
// Batched over blockIdx.z with two-level stride decomposition z = zb*hdiv+zh.
// EPI: 0 none | 1 +bias | 2 +bias, exact GELU | 3 +bias, +res (residual add)
// All M,N divisible by BM,BN; K divisible by 16. 256 threads.
// ---------------------------------------------------------------------------
template<int BM, int BN, int TM, int TN, bool BT, int EPI>
__global__ void __launch_bounds__(256, 2) sgemm_k(
    const float* __restrict__ A, const float* __restrict__ Bm,
    const float* __restrict__ bias, const float* __restrict__ res,
    float* __restrict__ Co,
    int K, int lda, int ldb, int ldc, int hdiv,
    long sAo, long sAi, long sBo, long sBi, long sCo, long sCi)
{
    constexpr int BK = 16;
    constexpr int TX = BN / TN;              // threads along n
    static_assert(TX * (BM / TM) == 256, "thread count");
    static_assert((TM & 1) == 0 && (TN & 1) == 0, "even frags");

    const int tid  = threadIdx.x;
    const int tcol = tid % TX;
    const int trow = tid / TX;

    const int z  = blockIdx.z;
    const int zb = z / hdiv;
    const int zh = z - zb * hdiv;
    const float* Ab = A  + zb * sAo + zh * sAi;
    const float* Bb = Bm + zb * sBo + zh * sBi;
    float*       Cb = Co + zb * sCo + zh * sCi;

    const int row0 = blockIdx.y * BM;
    const int col0 = blockIdx.x * BN;

    __shared__ float As[BK][BM + 4];
    __shared__ float Bs[BK][BN + 4];

    float acc[TM][TN];
    #pragma unroll
    for (int i = 0; i < TM; i++)
        #pragma unroll
        for (int j = 0; j < TN; j++) acc[i][j] = 0.f;

    for (int k0 = 0; k0 < K; k0 += BK) {
        // ---- load A tile (BM x BK), transpose into As[k][m]
        #pragma unroll
        for (int i = 0; i < (BM * BK) / 1024; i++) {
            int f  = tid + i * 256;
            int m  = f >> 2;              // BK/4 = 4 float4 per row
            int kq = (f & 3) << 2;
            const float4 v = *reinterpret_cast<const float4*>(
                Ab + (long)(row0 + m) * lda + k0 + kq);
            As[kq + 0][m] = v.x; As[kq + 1][m] = v.y;
            As[kq + 2][m] = v.z; As[kq + 3][m] = v.w;
        }
        // ---- load B tile
        if constexpr (!BT) {
            #pragma unroll
            for (int i = 0; i < (BN * BK) / 1024; i++) {
                int f  = tid + i * 256;
                int n  = f >> 2;
                int kq = (f & 3) << 2;
                const float4 v = *reinterpret_cast<const float4*>(
                    Bb + (long)(col0 + n) * ldb + k0 + kq);
                Bs[kq + 0][n] = v.x; Bs[kq + 1][n] = v.y;
                Bs[kq + 2][n] = v.z; Bs[kq + 3][n] = v.w;
            }
        } else {
            #pragma unroll
            for (int i = 0; i < (BK * BN) / 1024; i++) {
                int f  = tid + i * 256;
                int k  = f / (BN / 4);
                int nq = (f % (BN / 4)) << 2;
                *reinterpret_cast<float4*>(&Bs[k][nq]) =
                    *reinterpret_cast<const float4*>(
                        Bb + (long)(k0 + k) * ldb + col0 + nq);
            }
        }
        __syncthreads();

        #pragma unroll
        for (int kk = 0; kk < BK; kk++) {
            float ar[TM], br[TN];
            *reinterpret_cast<float4*>(&ar[0]) =
                *reinterpret_cast<const float4*>(&As[kk][trow * (TM / 2)]);
            *reinterpret_cast<float4*>(&ar[TM / 2]) =
                *reinterpret_cast<const float4*>(&As[kk][BM / 2 + trow * (TM / 2)]);
            if constexpr (TN == 8) {
                *reinterpret_cast<float4*>(&br[0]) =
                    *reinterpret_cast<const float4*>(&Bs[kk][tcol * 4]);
                *reinterpret_cast<float4*>(&br[4]) =
                    *reinterpret_cast<const float4*>(&Bs[kk][BN / 2 + tcol * 4]);
            } else {
                *reinterpret_cast<float2*>(&br[0]) =
                    *reinterpret_cast<const float2*>(&Bs[kk][tcol * 2]);
                *reinterpret_cast<float2*>(&br[2]) =
                    *reinterpret_cast<const float2*>(&Bs[kk][BN / 2 + tcol * 2]);
            }
            #pragma unroll
            for (int i = 0; i < TM; i++)
                #pragma unroll
                for (int j = 0; j < TN; j++)
                    acc[i][j] = fmaf(ar[i], br[j], acc[i][j]);
        }
        __syncthreads();
    }

    // ---- epilogue
    #pragma unroll
    for (int hi = 0; hi < 2; hi++)
        #pragma unroll
        for (int i = 0; i < TM / 2; i++) {
            const int  m  = row0 + hi * (BM / 2) + trow * (TM / 2) + i;
            const long ro = (long)m * ldc;
            #pragma unroll
            for (int hj = 0; hj < 2; hj++)
                #pragma unroll
                for (int j = 0; j < TN / 2; j++) {
                    const int n = col0 + hj * (BN / 2) + tcol * (TN / 2) + j;
                    float v = acc[hi * (TM / 2) + i][hj * (TN / 2) + j];
                    if constexpr (EPI >= 1) v += bias[n];
                    if constexpr (EPI == 2)
                        v = 0.5f * v * (1.f + erff(v * 0.70710678118654752f));
                    if constexpr (EPI == 3) v += res[ro + n];
                    Cb[ro + n] = v;
                }
        }
}

// ---------------------------------------------------------------------------
// Host launch — 110 kernel launches, all graph-capturable.
// ---------------------------------------------------------------------------
extern "C" void kernel_launch(void* const* d_in, const int* in_sizes, int n_in,
                              void* d_out, int out_size) {
    (void)in_sizes; (void)n_in; (void)out_size;
    const float* x     = (const float*)d_in[0];
    const float* posx  = (const float*)d_in[1];
    const float* qkvw  = (const float*)d_in[2];
    const float* qkvb  = (const float*)d_in[3];
    const float* projw = (const float*)d_in[4];
    const float* projb = (const float*)d_in[5];
    const float* f1w   = (const float*)d_in[6];
    const float* f1b   = (const float*)d_in[7];
    const float* f2w   = (const float*)d_in[8];
    const float* f2b   = (const float*)d_in[9];
    const float* ln1g  = (const float*)d_in[10];
    const float* ln1b  = (const float*)d_in[11];
    const float* ln2g  = (const float*)d_in[12];
    const float* ln2b  = (const float*)d_in[13];
    const float* nfg   = (const float*)d_in[14];
    const float* nfb   = (const float*)d_in[15];
    float* out = (float*)d_out;

    float *px, *pln, *pqkv, *pao, *pffn, *psc;
    cudaGetSymbolAddress((void**)&px,   g_x);
    cudaGetSymbolAddress((void**)&pln,  g_ln);
    cudaGetSymbolAddress((void**)&pqkv, g_qkv);
    cudaGetSymbolAddress((void**)&pao,  g_ao);
    cudaGetSymbolAddress((void**)&pffn, g_ffn);
    cudaGetSymbolAddress((void**)&psc,  g_sc);

    // x = x + pos_x (once)
    add_k<<<(M_ * C_) / 256, 256>>>(px, x, posx);

    for (int l = 0; l < D_; l++) {
        const float* qw = qkvw  + (long)l * C3_ * C_;
        const float* qb = qkvb  + (long)l * C3_;
        const float* pw = projw + (long)l * C_ * C_;
        const float* pb = projb + (long)l * C_;
        const float* w1 = f1w   + (long)l * FF_ * C_;
        const float* b1 = f1b   + (long)l * FF_;
        const float* w2 = f2w   + (long)l * C_ * FF_;
        const float* b2 = f2b   + (long)l * C_;

        // h = LN1(x)
        ln_k<<<M_, 256>>>(px, ln1g + l * C_, ln1b + l * C_, pln);

        // qkv = h @ qkv_w^T + qkv_b : [4096,2304]
        sgemm_k<128,128,8,8,false,1><<<dim3(C3_/128, M_/128, 1), 256>>>(
            pln, qw, qb, nullptr, pqkv,
            C_, C_, C_, C3_, 1, 0,0,0,0,0,0);

        // S = Q K^T : batched (b,h), [1024,1024], K=64
        sgemm_k<128,128,8,8,false,0><<<dim3(N_/128, N_/128, B_*H_), 256>>>(
            pqkv, pqkv + C_, nullptr, nullptr, psc,
            HD_, C3_, C3_, N_, H_,
            (long)N_ * C3_, HD_, (long)N_ * C3_, HD_,
            (long)H_ * N_ * N_, (long)N_ * N_);

        // softmax(S * scale) rows
        softmax_k<<<B_ * H_ * N_, 256>>>(psc);

        // O = P V : batched, [1024,64], K=1024 (V accessed transposed)
        sgemm_k<128,64,8,4,true,0><<<dim3(1, N_/128, B_*H_), 256>>>(
            psc, pqkv + 2 * C_, nullptr, nullptr, pao,
            N_, N_, C3_, C_, H_,
            (long)H_ * N_ * N_, (long)N_ * N_, (long)N_ * C3_, HD_,
            (long)N_ * C_, HD_);

        // x = x + (O @ proj_w^T + proj_b)
        sgemm_k<128,128,8,8,false,3><<<dim3(C_/128, M_/128, 1), 256>>>(
            pao, pw, pb, px, px,
            C_, C_, C_, C_, 1, 0,0,0,0,0,0);

        // h2 = LN2(x)
        ln_k<<<M_, 256>>>(px, ln2g + l * C_, ln2b + l * C_, pln);

        // hid = gelu(h2 @ fc1_w^T + fc1_b) : [4096,3072]
        sgemm_k<128,128,8,8,false,2><<<dim3(FF_/128, M_/128, 1), 256>>>(
            pln, w1, b1, nullptr, pffn,
            C_, C_, C_, FF_, 1, 0,0,0,0,0,0);

        // x = x + (hid @ fc2_w^T + fc2_b)
        sgemm_k<128,128,8,8,false,3><<<dim3(C_/128, M_/128, 1), 256>>>(
            pffn, w2, b2, px, px,
            FF_, FF_, FF_, C_, 1, 0,0,0,0,0,0);
    }

    // final post-norm -> output
    ln_k<<<M_, 256>>>(px, nfg, nfb, out);
}